// round 13
// baseline (speedup 1.0000x reference)
#include <cuda_runtime.h>
#include <cuda_fp16.h>
#include <cstdint>

// ---------------- problem constants ----------------
#define BB    16
#define KK    2048
#define DD    512
#define INNER 1024
#define W2    (2*INNER)    // combined a|b row stride (halves)
#define KW    5
#define MM    (BB*KK)      // 32768
#define MH    (MM/2)       // rows per half (16384)
#define BH    (BB/2)       // batches per half (8)
#define EPSV  1e-5f
#define NC    128          // scan chunks
#define CL    (KK/NC)      // 16
#define RSU2  (W2/4)       // uint2 per ab row (512)
#define USU2  (INNER/4)    // uint2 per g row (256)

// ---------------- scratch (device globals) ----------------
__device__ __half  g_ab [(size_t)MM * W2];     // [M, 2048]: a | b (fp16) 128MB
__device__ __half  g_h16[(size_t)MM * DD];     // rmsnorm out (fp16)
__device__ __half  g_g16[(size_t)MM * INNER];  // scan out    (fp16)
__device__ __half  g_w2 [W2 * DD];             // [Wa;Wb] fp16
__device__ __half  g_wo16[DD * INNER];
__device__ float   g_state[BB * NC * INNER];   // chunk-local final states
__device__ float   g_sin  [BB * NC * INNER];   // carried-in states

__device__ __forceinline__ uint32_t smem_u32(const void* p) {
    uint32_t a;
    asm("{ .reg .u64 t; cvta.to.shared.u64 t, %1; cvt.u32.u64 %0, t; }"
        : "=r"(a) : "l"(p));
    return a;
}

// fast single-MUFU silu: 0.5c + 0.5c*tanh(0.5c)
__device__ __forceinline__ float silu_fast(float c) {
    float h = 0.5f * c;
    float t;
    asm("tanh.approx.f32 %0, %1;" : "=f"(t) : "f"(h));
    return fmaf(h, t, h);
}

// 4-half <-> 4-float helpers
__device__ __forceinline__ void h4_to_f4(uint2 v, float* f) {
    __half2 lo = *reinterpret_cast<__half2*>(&v.x);
    __half2 hi = *reinterpret_cast<__half2*>(&v.y);
    float2 a = __half22float2(lo), b = __half22float2(hi);
    f[0] = a.x; f[1] = a.y; f[2] = b.x; f[3] = b.y;
}
__device__ __forceinline__ uint2 f4_to_h4(const float* f) {
    __half2 lo = __floats2half2_rn(f[0], f[1]);
    __half2 hi = __floats2half2_rn(f[2], f[3]);
    uint2 r;
    r.x = *reinterpret_cast<uint32_t*>(&lo);
    r.y = *reinterpret_cast<uint32_t*>(&hi);
    return r;
}

// ---------------- rmsnorm -> fp16 ----------------
__global__ __launch_bounds__(256) void rmsnorm_kernel(
    const float* __restrict__ x, const float* __restrict__ w,
    __half* __restrict__ h16)
{
    int row  = blockIdx.x * 8 + (threadIdx.x >> 5);
    int lane = threadIdx.x & 31;
    const float4* xp = reinterpret_cast<const float4*>(x + (size_t)row * DD);
    const float4* wp = reinterpret_cast<const float4*>(w);

    float4 v[4];
    float ss = 0.f;
#pragma unroll
    for (int j = 0; j < 4; j++) {
        v[j] = xp[lane + 32 * j];
        ss += v[j].x * v[j].x + v[j].y * v[j].y + v[j].z * v[j].z + v[j].w * v[j].w;
    }
#pragma unroll
    for (int off = 16; off > 0; off >>= 1)
        ss += __shfl_xor_sync(0xffffffffu, ss, off);

    float r = rsqrtf(ss * (1.0f / DD) + EPSV);

    __half* hb = h16 + (size_t)row * DD;
#pragma unroll
    for (int j = 0; j < 4; j++) {
        float4 wv = wp[lane + 32 * j];
        int col = (lane + 32 * j) * 4;
        __half2* hp = reinterpret_cast<__half2*>(hb + col);
        hp[0] = __floats2half2_rn(v[j].x * r * wv.x, v[j].y * r * wv.y);
        hp[1] = __floats2half2_rn(v[j].z * r * wv.z, v[j].w * r * wv.w);
    }
}

// ---------------- combined fp32 -> fp16 cast (all three weights) ------------
#define CVT_N4 (INNER * DD / 4)
__global__ __launch_bounds__(256) void cvt_all_kernel(
    const float* __restrict__ Wa, const float* __restrict__ Wb,
    const float* __restrict__ Wo,
    __half* __restrict__ w2, __half* __restrict__ wo16)
{
    int i = blockIdx.x * 256 + threadIdx.x;
    const float* src;
    __half* dst;
    int o;
    if (i < CVT_N4)            { src = Wa; dst = w2;                        o = i; }
    else if (i < 2 * CVT_N4)   { src = Wb; dst = w2 + (size_t)INNER * DD;   o = i - CVT_N4; }
    else                       { src = Wo; dst = wo16;                      o = i - 2 * CVT_N4; }
    float4 v = reinterpret_cast<const float4*>(src)[o];
    __half2* d = reinterpret_cast<__half2*>(dst) + o * 2;
    d[0] = __floats2half2_rn(v.x, v.y);
    d[1] = __floats2half2_rn(v.z, v.w);
}

// ---------------- HMMA fp16 GEMM with ldmatrix, 3-stage pipeline ------------
#define RS 40
#define TILE_H (128 * RS)
#define TB (TILE_H * 2)
#define STAGE_B (2 * TB)
#define NSTAGE 3
#define GEMM_SMEM_BYTES (NSTAGE * STAGE_B)   // 61440

#define MMA_F16(c, a, b)                                                \
    asm volatile(                                                       \
        "mma.sync.aligned.m16n8k16.row.col.f32.f16.f16.f32 "            \
        "{%0,%1,%2,%3}, {%4,%5,%6,%7}, {%8,%9}, {%0,%1,%2,%3};"         \
        : "+f"((c)[0]), "+f"((c)[1]), "+f"((c)[2]), "+f"((c)[3])        \
        : "r"((a)[0]), "r"((a)[1]), "r"((a)[2]), "r"((a)[3]),           \
          "r"((b)[0]), "r"((b)[1]))

#define LDSM4(r0, r1, r2, r3, addr)                                     \
    asm volatile("ldmatrix.sync.aligned.m8n8.x4.shared.b16 "            \
                 "{%0,%1,%2,%3}, [%4];"                                 \
                 : "=r"(r0), "=r"(r1), "=r"(r2), "=r"(r3) : "r"(addr))

template <bool HALF_OUT>
__global__ __launch_bounds__(256, 2) void gemm_f16(
    const __half* __restrict__ A, const __half* __restrict__ B,
    void* __restrict__ Cv, const float* __restrict__ res, int N, int K)
{
    extern __shared__ uint16_t sm[];

    const int tid  = threadIdx.x;
    const int lane = tid & 31;
    const int wid  = tid >> 5;
    const int wm   = wid >> 2;
    const int wn   = wid & 3;
    const int r    = lane >> 2;
    const int cp   = (lane & 3) * 2;

    const size_t mBase = (size_t)blockIdx.y * 128;
    const size_t nBase = (size_t)blockIdx.x * 128;

    const __half* srcA = A + mBase * K;
    const __half* srcB = B + nBase * K;

    const uint32_t smem_base = smem_u32(sm);

    const uint32_t aLaneOff =
        (uint32_t)(((wm * 64 + ((lane >> 3) & 1) * 8 + (lane & 7)) * RS
                    + (lane >> 4) * 8) * 2);
    const uint32_t bLaneOff =
        (uint32_t)(((wn * 32 + ((lane >> 4) & 1) * 8 + (lane & 7)) * RS
                    + ((lane >> 3) & 1) * 8) * 2);

    const int lrow0 = tid >> 2;
    const int lseg  = tid & 3;
    auto load_stage = [&](int s, int kt) {
        uint32_t sb = smem_base + (uint32_t)s * STAGE_B;
#pragma unroll
        for (int rep = 0; rep < 2; rep++) {
            int row = lrow0 + rep * 64;
            uint32_t off = row * (RS * 2) + lseg * 16;
            size_t go = (size_t)row * K + kt * 32 + lseg * 8;
            asm volatile("cp.async.cg.shared.global [%0], [%1], 16;"
                         :: "r"(sb + off), "l"(srcA + go));
            asm volatile("cp.async.cg.shared.global [%0], [%1], 16;"
                         :: "r"(sb + TB + off), "l"(srcB + go));
        }
        asm volatile("cp.async.commit_group;" ::: "memory");
    };

    float acc[4][4][4];
#pragma unroll
    for (int i = 0; i < 4; i++)
#pragma unroll
        for (int j = 0; j < 4; j++)
#pragma unroll
            for (int q = 0; q < 4; q++) acc[i][j][q] = 0.f;

    const int nkt = K >> 5;

    load_stage(0, 0);
    load_stage(1, 1);

    int sc = 0;
    for (int kt = 0; kt < nkt; kt++) {
        if (kt + 1 < nkt) {
            asm volatile("cp.async.wait_group 1;" ::: "memory");
        } else {
            asm volatile("cp.async.wait_group 0;" ::: "memory");
        }
        __syncthreads();

        if (kt + 2 < nkt) {
            int s2 = sc + 2; if (s2 >= NSTAGE) s2 -= NSTAGE;
            load_stage(s2, kt + 2);
        }

        uint32_t sb = smem_base + (uint32_t)sc * STAGE_B;

#pragma unroll
        for (int k16 = 0; k16 < 32; k16 += 16) {
            uint32_t bh[4][2];
#pragma unroll
            for (int j = 0; j < 2; j++) {
                uint32_t ad = sb + TB + bLaneOff
                            + (uint32_t)((j * 16 * RS + k16) * 2);
                LDSM4(bh[2*j][0], bh[2*j][1], bh[2*j+1][0], bh[2*j+1][1], ad);
            }
#pragma unroll
            for (int mi = 0; mi < 4; mi++) {
                uint32_t a4[4];
                uint32_t ad = sb + aLaneOff + (uint32_t)((mi * 16 * RS + k16) * 2);
                LDSM4(a4[0], a4[1], a4[2], a4[3], ad);
#pragma unroll
                for (int ni = 0; ni < 4; ni++)
                    MMA_F16(acc[mi][ni], a4, bh[ni]);
            }
        }
        __syncthreads();
        if (++sc == NSTAGE) sc = 0;
    }

#pragma unroll
    for (int mi = 0; mi < 4; mi++) {
        size_t row0 = mBase + wm * 64 + mi * 16 + r;
#pragma unroll
        for (int ni = 0; ni < 4; ni++) {
            size_t col = nBase + wn * 32 + ni * 8 + cp;
            if (HALF_OUT) {
                __half* C = (__half*)Cv;
                *reinterpret_cast<__half2*>(C + row0 * N + col) =
                    __floats2half2_rn(acc[mi][ni][0], acc[mi][ni][1]);
                *reinterpret_cast<__half2*>(C + (row0 + 8) * N + col) =
                    __floats2half2_rn(acc[mi][ni][2], acc[mi][ni][3]);
            } else {
                float* C = (float*)Cv;
                float2 v0 = make_float2(acc[mi][ni][0], acc[mi][ni][1]);
                float2 v1 = make_float2(acc[mi][ni][2], acc[mi][ni][3]);
                if (res) {
                    float2 r0 = *reinterpret_cast<const float2*>(res + row0 * N + col);
                    float2 r1 = *reinterpret_cast<const float2*>(res + (row0 + 8) * N + col);
                    v0.x += r0.x; v0.y += r0.y;
                    v1.x += r1.x; v1.y += r1.y;
                }
                *reinterpret_cast<float2*>(C + row0 * N + col) = v0;
                *reinterpret_cast<float2*>(C + (row0 + 8) * N + col) = v1;
            }
        }
    }
}

// ---------------- scan pass 1: conv+silu -> chunk states only ---------------
// Operates on BH batches (pointers pre-offset). Block = (batch, chunk).
__global__ __launch_bounds__(256, 3) void scan_state_kernel(
    const uint2* __restrict__ ab,
    const float* __restrict__ conv_w, const float* __restrict__ conv_b,
    const float* __restrict__ alpha, const float* __restrict__ beta,
    float* __restrict__ S)
{
    const int c = blockIdx.x & (NC - 1);
    const int b = blockIdx.x >> 7;
    const int t = threadIdx.x;
    const int i0 = t * 4;

    float w0[4], w1[4], w2[4], w3[4], w4[4], cb[4], as[4], bt[4];
#pragma unroll
    for (int l = 0; l < 4; l++) {
        w0[l] = conv_w[(i0+l)*KW+0];
        w1[l] = conv_w[(i0+l)*KW+1];
        w2[l] = conv_w[(i0+l)*KW+2];
        w3[l] = conv_w[(i0+l)*KW+3];
        w4[l] = conv_w[(i0+l)*KW+4];
        cb[l] = conv_b[i0+l];
        as[l] = 1.0f / (1.0f + __expf(-alpha[i0+l]));
        bt[l] = beta[i0+l];
    }

    const uint2* col = ab + (size_t)b * KK * RSU2 + t;
    const int k0 = c * CL;

    float xm2[4] = {0,0,0,0}, xm1[4] = {0,0,0,0}, x0[4], x1[4], s[4] = {0,0,0,0};
    if (c > 0) {
        h4_to_f4(col[(size_t)(k0-2) * RSU2], xm2);
        h4_to_f4(col[(size_t)(k0-1) * RSU2], xm1);
    }
    h4_to_f4(col[(size_t)k0 * RSU2], x0);
    h4_to_f4(col[(size_t)(k0+1) * RSU2], x1);

#pragma unroll
    for (int k = 0; k < CL; k += 4) {
        uint2 xr[4];
#pragma unroll
        for (int j = 0; j < 4; j++) {
            int kk = k0 + k + 2 + j;
            xr[j] = (kk < KK) ? col[(size_t)kk * RSU2] : make_uint2(0u, 0u);
        }
#pragma unroll
        for (int j = 0; j < 4; j++) {
            float x2[4];
            h4_to_f4(xr[j], x2);
#pragma unroll
            for (int l = 0; l < 4; l++) {
                float cc = fmaf(w0[l], xm2[l], fmaf(w1[l], xm1[l],
                           fmaf(w2[l], x0[l], fmaf(w3[l], x1[l],
                           fmaf(w4[l], x2[l], cb[l])))));
                float uu = silu_fast(cc);
                s[l] = fmaf(as[l], s[l], bt[l] * uu);
                xm2[l] = xm1[l]; xm1[l] = x0[l]; x0[l] = x1[l]; x1[l] = x2[l];
            }
        }
    }

    *reinterpret_cast<float4*>(&S[((size_t)b * NC + c) * INNER + i0]) =
        make_float4(s[0], s[1], s[2], s[3]);
}

// ---------------- scan pass 2: prefix of chunk states (BH batches) ----------
__global__ __launch_bounds__(256) void scan_prefix_kernel(
    const float* __restrict__ S, const float* __restrict__ alpha,
    float* __restrict__ Sin)
{
    int idx = blockIdx.x * 256 + threadIdx.x;   // 0 .. BH*INNER-1
    int i = idx & (INNER - 1);
    int b = idx >> 10;

    float a = 1.0f / (1.0f + __expf(-alpha[i]));
    float aL = a;
#pragma unroll
    for (int q = 0; q < 4; q++) aL *= aL;       // a^16

    float s = 0.f;
#pragma unroll
    for (int c = 0; c < NC; c++) {
        size_t o = ((size_t)b * NC + c) * INNER + i;
        Sin[o] = s;
        s = fmaf(aL, s, S[o]);
    }
}

// ---------------- scan pass 3: recompute conv+silu, apply, gate -> g --------
__global__ __launch_bounds__(256, 3) void scan_apply_kernel(
    const uint2* __restrict__ ab,
    const float* __restrict__ Sin,
    uint2* __restrict__ g,
    const float* __restrict__ conv_w, const float* __restrict__ conv_b,
    const float* __restrict__ alpha, const float* __restrict__ beta,
    const float* __restrict__ gamma, const float* __restrict__ delta)
{
    const int c = blockIdx.x & (NC - 1);
    const int b = blockIdx.x >> 7;
    const int t = threadIdx.x;
    const int i0 = t * 4;

    float w0[4], w1[4], w2[4], w3[4], w4[4], cb[4], as[4], bt[4], gm[4], dl[4];
#pragma unroll
    for (int l = 0; l < 4; l++) {
        w0[l] = conv_w[(i0+l)*KW+0];
        w1[l] = conv_w[(i0+l)*KW+1];
        w2[l] = conv_w[(i0+l)*KW+2];
        w3[l] = conv_w[(i0+l)*KW+3];
        w4[l] = conv_w[(i0+l)*KW+4];
        cb[l] = conv_b[i0+l];
        as[l] = 1.0f / (1.0f + __expf(-alpha[i0+l]));
        bt[l] = beta[i0+l];
        gm[l] = gamma[i0+l];
        dl[l] = delta[i0+l];
    }

    const uint2* col = ab + (size_t)b * KK * RSU2 + t;
    const uint2* bp  = col + (RSU2 / 2);
    uint2* gp = g + (size_t)b * KK * USU2 + t;
    const int k0 = c * CL;

    float s[4];
    {
        float4 sv = *reinterpret_cast<const float4*>(
            &Sin[((size_t)b * NC + c) * INNER + i0]);
        s[0] = sv.x; s[1] = sv.y; s[2] = sv.z; s[3] = sv.w;
    }

    float xm2[4] = {0,0,0,0}, xm1[4] = {0,0,0,0}, x0[4], x1[4];
    if (c > 0) {
        h4_to_f4(col[(size_t)(k0-2) * RSU2], xm2);
        h4_to_f4(col[(size_t)(k0-1) * RSU2], xm1);
    }
    h4_to_f4(col[(size_t)k0 * RSU2], x0);
    h4_to_f4(col[(size_t)(k0+1) * RSU2], x1);

#pragma unroll
    for (int k = 0; k < CL; k += 4) {
        uint2 xr[4], br[4];
#pragma unroll
        for (int j = 0; j < 4; j++) {
            int kk = k0 + k + 2 + j;
            xr[j] = (kk < KK) ? col[(size_t)kk * RSU2] : make_uint2(0u, 0u);
        }
#pragma unroll
        for (int j = 0; j < 4; j++)
            br[j] = bp[(size_t)(k0 + k + j) * RSU2];
#pragma unroll
        for (int j = 0; j < 4; j++) {
            float x2[4], bf[4], gf[4];
            h4_to_f4(xr[j], x2);
            h4_to_f4(br[j], bf);
#pragma unroll
            for (int l = 0; l < 4; l++) {
                float cc = fmaf(w0[l], xm2[l], fmaf(w1[l], xm1[l],
                           fmaf(w2[l], x0[l], fmaf(w3[l], x1[l],
                           fmaf(w4[l], x2[l], cb[l])))));
                float uu = silu_fast(cc);
                s[l] = fmaf(as[l], s[l], bt[l] * uu);
                float y = fmaf(gm[l], s[l], dl[l] * uu);
                gf[l] = y * bf[l];
                xm2[l] = xm1[l]; xm1[l] = x0[l]; x0[l] = x1[l]; x1[l] = x2[l];
            }
            gp[(size_t)(k0 + k + j) * USU2] = f4_to_h4(gf);
        }
    }
}

// ---------------- launch: fork scan+GEMM2 per batch-half -------------------
extern "C" void kernel_launch(void* const* d_in, const int* in_sizes, int n_in,
                              void* d_out, int out_size)
{
    const float* x      = (const float*)d_in[0];
    const float* norm_w = (const float*)d_in[1];
    const float* Wa     = (const float*)d_in[2];
    const float* Wb     = (const float*)d_in[3];
    const float* conv_w = (const float*)d_in[4];
    const float* conv_b = (const float*)d_in[5];
    const float* alpha  = (const float*)d_in[6];
    const float* beta   = (const float*)d_in[7];
    const float* gamma  = (const float*)d_in[8];
    const float* delta  = (const float*)d_in[9];
    const float* Wout   = (const float*)d_in[10];
    float* out = (float*)d_out;

    float *st, *sin;
    __half *ab, *h16, *g16, *w2, *wo16;
    cudaGetSymbolAddress((void**)&ab,   g_ab);
    cudaGetSymbolAddress((void**)&st,   g_state);
    cudaGetSymbolAddress((void**)&sin,  g_sin);
    cudaGetSymbolAddress((void**)&h16,  g_h16);
    cudaGetSymbolAddress((void**)&g16,  g_g16);
    cudaGetSymbolAddress((void**)&w2,   g_w2);
    cudaGetSymbolAddress((void**)&wo16, g_wo16);

    cudaFuncSetAttribute(gemm_f16<true>,
                         cudaFuncAttributeMaxDynamicSharedMemorySize, GEMM_SMEM_BYTES);
    cudaFuncSetAttribute(gemm_f16<false>,
                         cudaFuncAttributeMaxDynamicSharedMemorySize, GEMM_SMEM_BYTES);

    // side stream + fork/join events (created fresh; never destroyed while a
    // capture referencing them is in flight — no device memory involved)
    cudaStream_t s1;
    cudaStreamCreateWithFlags(&s1, cudaStreamNonBlocking);
    cudaEvent_t eh[2], ej;
    cudaEventCreateWithFlags(&eh[0], cudaEventDisableTiming);
    cudaEventCreateWithFlags(&eh[1], cudaEventDisableTiming);
    cudaEventCreateWithFlags(&ej,    cudaEventDisableTiming);

    // ---- main stream: rmsnorm, cvt, GEMM1 in two M-halves ----
    rmsnorm_kernel<<<MM / 8, 256>>>(x, norm_w, h16);
    cvt_all_kernel<<<(3 * CVT_N4) / 256, 256>>>(Wa, Wb, Wout, w2, wo16);

    dim3 grid1(W2 / 128, MH / 128);
    for (int h = 0; h < 2; h++) {
        gemm_f16<true><<<grid1, 256, GEMM_SMEM_BYTES>>>(
            h16 + (size_t)h * MH * DD, w2,
            ab + (size_t)h * MH * W2, nullptr, W2, DD);
        cudaEventRecord(eh[h], 0);
    }

    // ---- side stream: per-half scan chain + GEMM2 (overlaps GEMM1 h1) ----
    dim3 grid2(DD / 128, MH / 128);
    for (int h = 0; h < 2; h++) {
        cudaStreamWaitEvent(s1, eh[h], 0);
        const uint2* abh = (const uint2*)ab + (size_t)h * MH * RSU2;
        float* sth  = st  + (size_t)h * BH * NC * INNER;
        float* sinh_ = sin + (size_t)h * BH * NC * INNER;
        __half* g16h = g16 + (size_t)h * MH * INNER;

        scan_state_kernel<<<BH * NC, 256, 0, s1>>>(
            abh, conv_w, conv_b, alpha, beta, sth);
        scan_prefix_kernel<<<BH * INNER / 256, 256, 0, s1>>>(sth, alpha, sinh_);
        scan_apply_kernel<<<BH * NC, 256, 0, s1>>>(
            abh, sinh_, (uint2*)g16h, conv_w, conv_b,
            alpha, beta, gamma, delta);

        gemm_f16<false><<<grid2, 256, GEMM_SMEM_BYTES, s1>>>(
            g16h, wo16,
            out + (size_t)h * MH * DD,
            x + (size_t)h * MH * DD, DD, INNER);
    }

    // ---- join back to main stream ----
    cudaEventRecord(ej, s1);
    cudaStreamWaitEvent(0, ej, 0);
}

// round 14
// speedup vs baseline: 1.1073x; 1.1073x over previous
#include <cuda_runtime.h>
#include <cuda_fp16.h>
#include <cstdint>

// ---------------- problem constants ----------------
#define BB    16
#define KK    2048
#define DD    512
#define INNER 1024
#define W2    (2*INNER)    // combined a|b row stride (halves)
#define KW    5
#define MM    (BB*KK)      // 32768
#define EPSV  1e-5f
#define NC    128          // scan chunks
#define CL    (KK/NC)      // 16
#define RSU2  (W2/4)       // uint2 per ab row (512)
#define USU2  (INNER/4)    // uint2 per g row (256)

// ---------------- scratch (device globals) ----------------
__device__ __half  g_ab [(size_t)MM * W2];     // [M, 2048]: a | b (fp16) 128MB
__device__ __half  g_h16[(size_t)MM * DD];     // rmsnorm out (fp16)
__device__ __half  g_g16[(size_t)MM * INNER];  // scan out    (fp16)
__device__ __half  g_w2 [W2 * DD];             // [Wa;Wb] fp16
__device__ __half  g_wo16[DD * INNER];
__device__ float   g_state[BB * NC * INNER];   // chunk-local final states
__device__ float   g_sin  [BB * NC * INNER];   // carried-in states

__device__ __forceinline__ uint32_t smem_u32(const void* p) {
    uint32_t a;
    asm("{ .reg .u64 t; cvta.to.shared.u64 t, %1; cvt.u32.u64 %0, t; }"
        : "=r"(a) : "l"(p));
    return a;
}

// fast single-MUFU silu: 0.5c + 0.5c*tanh(0.5c)
__device__ __forceinline__ float silu_fast(float c) {
    float h = 0.5f * c;
    float t;
    asm("tanh.approx.f32 %0, %1;" : "=f"(t) : "f"(h));
    return fmaf(h, t, h);
}

// 4-half <-> 4-float helpers
__device__ __forceinline__ void h4_to_f4(uint2 v, float* f) {
    __half2 lo = *reinterpret_cast<__half2*>(&v.x);
    __half2 hi = *reinterpret_cast<__half2*>(&v.y);
    float2 a = __half22float2(lo), b = __half22float2(hi);
    f[0] = a.x; f[1] = a.y; f[2] = b.x; f[3] = b.y;
}
__device__ __forceinline__ uint2 f4_to_h4(const float* f) {
    __half2 lo = __floats2half2_rn(f[0], f[1]);
    __half2 hi = __floats2half2_rn(f[2], f[3]);
    uint2 r;
    r.x = *reinterpret_cast<uint32_t*>(&lo);
    r.y = *reinterpret_cast<uint32_t*>(&hi);
    return r;
}

// ---------------- rmsnorm -> fp16 ----------------
__global__ __launch_bounds__(256) void rmsnorm_kernel(
    const float* __restrict__ x, const float* __restrict__ w,
    __half* __restrict__ h16)
{
    int row  = blockIdx.x * 8 + (threadIdx.x >> 5);
    int lane = threadIdx.x & 31;
    const float4* xp = reinterpret_cast<const float4*>(x + (size_t)row * DD);
    const float4* wp = reinterpret_cast<const float4*>(w);

    float4 v[4];
    float ss = 0.f;
#pragma unroll
    for (int j = 0; j < 4; j++) {
        v[j] = xp[lane + 32 * j];
        ss += v[j].x * v[j].x + v[j].y * v[j].y + v[j].z * v[j].z + v[j].w * v[j].w;
    }
#pragma unroll
    for (int off = 16; off > 0; off >>= 1)
        ss += __shfl_xor_sync(0xffffffffu, ss, off);

    float r = rsqrtf(ss * (1.0f / DD) + EPSV);

    __half* hb = h16 + (size_t)row * DD;
#pragma unroll
    for (int j = 0; j < 4; j++) {
        float4 wv = wp[lane + 32 * j];
        int col = (lane + 32 * j) * 4;
        __half2* hp = reinterpret_cast<__half2*>(hb + col);
        hp[0] = __floats2half2_rn(v[j].x * r * wv.x, v[j].y * r * wv.y);
        hp[1] = __floats2half2_rn(v[j].z * r * wv.z, v[j].w * r * wv.w);
    }
}

// ---------------- combined fp32 -> fp16 cast (all three weights) ------------
#define CVT_N4 (INNER * DD / 4)
__global__ __launch_bounds__(256) void cvt_all_kernel(
    const float* __restrict__ Wa, const float* __restrict__ Wb,
    const float* __restrict__ Wo,
    __half* __restrict__ w2, __half* __restrict__ wo16)
{
    int i = blockIdx.x * 256 + threadIdx.x;
    const float* src;
    __half* dst;
    int o;
    if (i < CVT_N4)            { src = Wa; dst = w2;                        o = i; }
    else if (i < 2 * CVT_N4)   { src = Wb; dst = w2 + (size_t)INNER * DD;   o = i - CVT_N4; }
    else                       { src = Wo; dst = wo16;                      o = i - 2 * CVT_N4; }
    float4 v = reinterpret_cast<const float4*>(src)[o];
    __half2* d = reinterpret_cast<__half2*>(dst) + o * 2;
    d[0] = __floats2half2_rn(v.x, v.y);
    d[1] = __floats2half2_rn(v.z, v.w);
}

// ---------------- HMMA fp16 GEMM with ldmatrix, 4-stage pipeline ------------
// One __syncthreads per iteration; wait_group 2 keeps 2 stages in flight.
#define RS 40
#define TILE_H (128 * RS)
#define TB (TILE_H * 2)
#define STAGE_B (2 * TB)
#define NSTAGE 4
#define GEMM_SMEM_BYTES (NSTAGE * STAGE_B)   // 81920

#define MMA_F16(c, a, b)                                                \
    asm volatile(                                                       \
        "mma.sync.aligned.m16n8k16.row.col.f32.f16.f16.f32 "            \
        "{%0,%1,%2,%3}, {%4,%5,%6,%7}, {%8,%9}, {%0,%1,%2,%3};"         \
        : "+f"((c)[0]), "+f"((c)[1]), "+f"((c)[2]), "+f"((c)[3])        \
        : "r"((a)[0]), "r"((a)[1]), "r"((a)[2]), "r"((a)[3]),           \
          "r"((b)[0]), "r"((b)[1]))

#define LDSM4(r0, r1, r2, r3, addr)                                     \
    asm volatile("ldmatrix.sync.aligned.m8n8.x4.shared.b16 "            \
                 "{%0,%1,%2,%3}, [%4];"                                 \
                 : "=r"(r0), "=r"(r1), "=r"(r2), "=r"(r3) : "r"(addr))

template <bool HALF_OUT>
__global__ __launch_bounds__(256, 2) void gemm_f16(
    const __half* __restrict__ A, const __half* __restrict__ B,
    void* __restrict__ Cv, const float* __restrict__ res, int N, int K)
{
    extern __shared__ uint16_t sm[];

    const int tid  = threadIdx.x;
    const int lane = tid & 31;
    const int wid  = tid >> 5;
    const int wm   = wid >> 2;
    const int wn   = wid & 3;
    const int r    = lane >> 2;
    const int cp   = (lane & 3) * 2;

    const size_t mBase = (size_t)blockIdx.y * 128;
    const size_t nBase = (size_t)blockIdx.x * 128;

    const __half* srcA = A + mBase * K;
    const __half* srcB = B + nBase * K;

    const uint32_t smem_base = smem_u32(sm);

    const uint32_t aLaneOff =
        (uint32_t)(((wm * 64 + ((lane >> 3) & 1) * 8 + (lane & 7)) * RS
                    + (lane >> 4) * 8) * 2);
    const uint32_t bLaneOff =
        (uint32_t)(((wn * 32 + ((lane >> 4) & 1) * 8 + (lane & 7)) * RS
                    + ((lane >> 3) & 1) * 8) * 2);

    const int lrow0 = tid >> 2;
    const int lseg  = tid & 3;
    auto load_stage = [&](int s, int kt) {
        uint32_t sb = smem_base + (uint32_t)s * STAGE_B;
#pragma unroll
        for (int rep = 0; rep < 2; rep++) {
            int row = lrow0 + rep * 64;
            uint32_t off = row * (RS * 2) + lseg * 16;
            size_t go = (size_t)row * K + kt * 32 + lseg * 8;
            asm volatile("cp.async.cg.shared.global [%0], [%1], 16;"
                         :: "r"(sb + off), "l"(srcA + go));
            asm volatile("cp.async.cg.shared.global [%0], [%1], 16;"
                         :: "r"(sb + TB + off), "l"(srcB + go));
        }
        asm volatile("cp.async.commit_group;" ::: "memory");
    };

    float acc[4][4][4];
#pragma unroll
    for (int i = 0; i < 4; i++)
#pragma unroll
        for (int j = 0; j < 4; j++)
#pragma unroll
            for (int q = 0; q < 4; q++) acc[i][j][q] = 0.f;

    const int nkt = K >> 5;

    load_stage(0, 0);
    load_stage(1, 1);
    load_stage(2, 2);

    int sc = 0;                       // stage of kt (kt % 4)
    for (int kt = 0; kt < nkt; kt++) {
        // wait until stage kt's group has landed
        int rem = nkt - 1 - kt;       // groups that may stay outstanding
        if (rem >= 2) {
            asm volatile("cp.async.wait_group 2;" ::: "memory");
        } else if (rem == 1) {
            asm volatile("cp.async.wait_group 1;" ::: "memory");
        } else {
            asm volatile("cp.async.wait_group 0;" ::: "memory");
        }
        __syncthreads();   // also guarantees all warps finished compute kt-1

        if (kt + 3 < nkt) {
            int s3 = sc + 3; if (s3 >= NSTAGE) s3 -= NSTAGE;
            load_stage(s3, kt + 3);   // overwrites stage kt-1 (safe post-sync)
        }

        uint32_t sb = smem_base + (uint32_t)sc * STAGE_B;

#pragma unroll
        for (int k16 = 0; k16 < 32; k16 += 16) {
            uint32_t bh[4][2];
#pragma unroll
            for (int j = 0; j < 2; j++) {
                uint32_t ad = sb + TB + bLaneOff
                            + (uint32_t)((j * 16 * RS + k16) * 2);
                LDSM4(bh[2*j][0], bh[2*j][1], bh[2*j+1][0], bh[2*j+1][1], ad);
            }
#pragma unroll
            for (int mi = 0; mi < 4; mi++) {
                uint32_t a4[4];
                uint32_t ad = sb + aLaneOff + (uint32_t)((mi * 16 * RS + k16) * 2);
                LDSM4(a4[0], a4[1], a4[2], a4[3], ad);
#pragma unroll
                for (int ni = 0; ni < 4; ni++)
                    MMA_F16(acc[mi][ni], a4, bh[ni]);
            }
        }
        if (++sc == NSTAGE) sc = 0;
    }

#pragma unroll
    for (int mi = 0; mi < 4; mi++) {
        size_t row0 = mBase + wm * 64 + mi * 16 + r;
#pragma unroll
        for (int ni = 0; ni < 4; ni++) {
            size_t col = nBase + wn * 32 + ni * 8 + cp;
            if (HALF_OUT) {
                __half* C = (__half*)Cv;
                *reinterpret_cast<__half2*>(C + row0 * N + col) =
                    __floats2half2_rn(acc[mi][ni][0], acc[mi][ni][1]);
                *reinterpret_cast<__half2*>(C + (row0 + 8) * N + col) =
                    __floats2half2_rn(acc[mi][ni][2], acc[mi][ni][3]);
            } else {
                float* C = (float*)Cv;
                float2 v0 = make_float2(acc[mi][ni][0], acc[mi][ni][1]);
                float2 v1 = make_float2(acc[mi][ni][2], acc[mi][ni][3]);
                if (res) {
                    float2 r0 = *reinterpret_cast<const float2*>(res + row0 * N + col);
                    float2 r1 = *reinterpret_cast<const float2*>(res + (row0 + 8) * N + col);
                    v0.x += r0.x; v0.y += r0.y;
                    v1.x += r1.x; v1.y += r1.y;
                }
                *reinterpret_cast<float2*>(C + row0 * N + col) = v0;
                *reinterpret_cast<float2*>(C + (row0 + 8) * N + col) = v1;
            }
        }
    }
}

// ---------------- scan pass 1: conv+silu -> chunk states only ---------------
__global__ __launch_bounds__(256, 3) void scan_state_kernel(
    const uint2* __restrict__ ab,
    const float* __restrict__ conv_w, const float* __restrict__ conv_b,
    const float* __restrict__ alpha, const float* __restrict__ beta,
    float* __restrict__ S)
{
    const int c = blockIdx.x & (NC - 1);
    const int b = blockIdx.x >> 7;
    const int t = threadIdx.x;
    const int i0 = t * 4;

    float w0[4], w1[4], w2[4], w3[4], w4[4], cb[4], as[4], bt[4];
#pragma unroll
    for (int l = 0; l < 4; l++) {
        w0[l] = conv_w[(i0+l)*KW+0];
        w1[l] = conv_w[(i0+l)*KW+1];
        w2[l] = conv_w[(i0+l)*KW+2];
        w3[l] = conv_w[(i0+l)*KW+3];
        w4[l] = conv_w[(i0+l)*KW+4];
        cb[l] = conv_b[i0+l];
        as[l] = 1.0f / (1.0f + __expf(-alpha[i0+l]));
        bt[l] = beta[i0+l];
    }

    const uint2* col = ab + (size_t)b * KK * RSU2 + t;
    const int k0 = c * CL;

    float xm2[4] = {0,0,0,0}, xm1[4] = {0,0,0,0}, x0[4], x1[4], s[4] = {0,0,0,0};
    if (c > 0) {
        h4_to_f4(col[(size_t)(k0-2) * RSU2], xm2);
        h4_to_f4(col[(size_t)(k0-1) * RSU2], xm1);
    }
    h4_to_f4(col[(size_t)k0 * RSU2], x0);
    h4_to_f4(col[(size_t)(k0+1) * RSU2], x1);

#pragma unroll
    for (int k = 0; k < CL; k += 4) {
        uint2 xr[4];
#pragma unroll
        for (int j = 0; j < 4; j++) {
            int kk = k0 + k + 2 + j;
            xr[j] = (kk < KK) ? col[(size_t)kk * RSU2] : make_uint2(0u, 0u);
        }
#pragma unroll
        for (int j = 0; j < 4; j++) {
            float x2[4];
            h4_to_f4(xr[j], x2);
#pragma unroll
            for (int l = 0; l < 4; l++) {
                float cc = fmaf(w0[l], xm2[l], fmaf(w1[l], xm1[l],
                           fmaf(w2[l], x0[l], fmaf(w3[l], x1[l],
                           fmaf(w4[l], x2[l], cb[l])))));
                float uu = silu_fast(cc);
                s[l] = fmaf(as[l], s[l], bt[l] * uu);
                xm2[l] = xm1[l]; xm1[l] = x0[l]; x0[l] = x1[l]; x1[l] = x2[l];
            }
        }
    }

    *reinterpret_cast<float4*>(&S[((size_t)b * NC + c) * INNER + i0]) =
        make_float4(s[0], s[1], s[2], s[3]);
}

// ---------------- scan pass 2: prefix of chunk states ----------------
__global__ __launch_bounds__(256) void scan_prefix_kernel(
    const float* __restrict__ S, const float* __restrict__ alpha,
    float* __restrict__ Sin)
{
    int idx = blockIdx.x * 256 + threadIdx.x;   // 0 .. BB*INNER-1
    int i = idx & (INNER - 1);
    int b = idx >> 10;

    float a = 1.0f / (1.0f + __expf(-alpha[i]));
    float aL = a;
#pragma unroll
    for (int q = 0; q < 4; q++) aL *= aL;       // a^16

    float s = 0.f;
#pragma unroll
    for (int c = 0; c < NC; c++) {
        size_t o = ((size_t)b * NC + c) * INNER + i;
        Sin[o] = s;
        s = fmaf(aL, s, S[o]);
    }
}

// ---------------- scan pass 3: recompute conv+silu, apply, gate -> g --------
__global__ __launch_bounds__(256, 3) void scan_apply_kernel(
    const uint2* __restrict__ ab,
    const float* __restrict__ Sin,
    uint2* __restrict__ g,
    const float* __restrict__ conv_w, const float* __restrict__ conv_b,
    const float* __restrict__ alpha, const float* __restrict__ beta,
    const float* __restrict__ gamma, const float* __restrict__ delta)
{
    const int c = blockIdx.x & (NC - 1);
    const int b = blockIdx.x >> 7;
    const int t = threadIdx.x;
    const int i0 = t * 4;

    float w0[4], w1[4], w2[4], w3[4], w4[4], cb[4], as[4], bt[4], gm[4], dl[4];
#pragma unroll
    for (int l = 0; l < 4; l++) {
        w0[l] = conv_w[(i0+l)*KW+0];
        w1[l] = conv_w[(i0+l)*KW+1];
        w2[l] = conv_w[(i0+l)*KW+2];
        w3[l] = conv_w[(i0+l)*KW+3];
        w4[l] = conv_w[(i0+l)*KW+4];
        cb[l] = conv_b[i0+l];
        as[l] = 1.0f / (1.0f + __expf(-alpha[i0+l]));
        bt[l] = beta[i0+l];
        gm[l] = gamma[i0+l];
        dl[l] = delta[i0+l];
    }

    const uint2* col = ab + (size_t)b * KK * RSU2 + t;
    const uint2* bp  = col + (RSU2 / 2);
    uint2* gp = g + (size_t)b * KK * USU2 + t;
    const int k0 = c * CL;

    float s[4];
    {
        float4 sv = *reinterpret_cast<const float4*>(
            &Sin[((size_t)b * NC + c) * INNER + i0]);
        s[0] = sv.x; s[1] = sv.y; s[2] = sv.z; s[3] = sv.w;
    }

    float xm2[4] = {0,0,0,0}, xm1[4] = {0,0,0,0}, x0[4], x1[4];
    if (c > 0) {
        h4_to_f4(col[(size_t)(k0-2) * RSU2], xm2);
        h4_to_f4(col[(size_t)(k0-1) * RSU2], xm1);
    }
    h4_to_f4(col[(size_t)k0 * RSU2], x0);
    h4_to_f4(col[(size_t)(k0+1) * RSU2], x1);

#pragma unroll
    for (int k = 0; k < CL; k += 4) {
        uint2 xr[4], br[4];
#pragma unroll
        for (int j = 0; j < 4; j++) {
            int kk = k0 + k + 2 + j;
            xr[j] = (kk < KK) ? col[(size_t)kk * RSU2] : make_uint2(0u, 0u);
        }
#pragma unroll
        for (int j = 0; j < 4; j++)
            br[j] = bp[(size_t)(k0 + k + j) * RSU2];
#pragma unroll
        for (int j = 0; j < 4; j++) {
            float x2[4], bf[4], gf[4];
            h4_to_f4(xr[j], x2);
            h4_to_f4(br[j], bf);
#pragma unroll
            for (int l = 0; l < 4; l++) {
                float cc = fmaf(w0[l], xm2[l], fmaf(w1[l], xm1[l],
                           fmaf(w2[l], x0[l], fmaf(w3[l], x1[l],
                           fmaf(w4[l], x2[l], cb[l])))));
                float uu = silu_fast(cc);
                s[l] = fmaf(as[l], s[l], bt[l] * uu);
                float y = fmaf(gm[l], s[l], dl[l] * uu);
                gf[l] = y * bf[l];
                xm2[l] = xm1[l]; xm1[l] = x0[l]; x0[l] = x1[l]; x1[l] = x2[l];
            }
            gp[(size_t)(k0 + k + j) * USU2] = f4_to_h4(gf);
        }
    }
}

// ---------------- launch (serialized, single stream) ------------------------
extern "C" void kernel_launch(void* const* d_in, const int* in_sizes, int n_in,
                              void* d_out, int out_size)
{
    const float* x      = (const float*)d_in[0];
    const float* norm_w = (const float*)d_in[1];
    const float* Wa     = (const float*)d_in[2];
    const float* Wb     = (const float*)d_in[3];
    const float* conv_w = (const float*)d_in[4];
    const float* conv_b = (const float*)d_in[5];
    const float* alpha  = (const float*)d_in[6];
    const float* beta   = (const float*)d_in[7];
    const float* gamma  = (const float*)d_in[8];
    const float* delta  = (const float*)d_in[9];
    const float* Wout   = (const float*)d_in[10];
    float* out = (float*)d_out;

    float *st, *sin;
    __half *ab, *h16, *g16, *w2, *wo16;
    cudaGetSymbolAddress((void**)&ab,   g_ab);
    cudaGetSymbolAddress((void**)&st,   g_state);
    cudaGetSymbolAddress((void**)&sin,  g_sin);
    cudaGetSymbolAddress((void**)&h16,  g_h16);
    cudaGetSymbolAddress((void**)&g16,  g_g16);
    cudaGetSymbolAddress((void**)&w2,   g_w2);
    cudaGetSymbolAddress((void**)&wo16, g_wo16);

    cudaFuncSetAttribute(gemm_f16<true>,
                         cudaFuncAttributeMaxDynamicSharedMemorySize, GEMM_SMEM_BYTES);
    cudaFuncSetAttribute(gemm_f16<false>,
                         cudaFuncAttributeMaxDynamicSharedMemorySize, GEMM_SMEM_BYTES);

    // 1) rmsnorm -> fp16
    rmsnorm_kernel<<<MM / 8, 256>>>(x, norm_w, h16);

    // 2) all weight conversions in one launch
    cvt_all_kernel<<<(3 * CVT_N4) / 256, 256>>>(Wa, Wb, Wout, w2, wo16);

    // 3) [a|b] = h @ [Wa;Wb]^T   (M=32768, N=2048, K=512), fp16 out
    {
        dim3 grid(W2 / 128, MM / 128);
        gemm_f16<true><<<grid, 256, GEMM_SMEM_BYTES>>>(h16, w2, ab, nullptr, W2, DD);
    }

    // 4) chunked scan: states, prefix, apply(recompute silu)
    scan_state_kernel<<<BB * NC, 256>>>(
        (const uint2*)ab, conv_w, conv_b, alpha, beta, st);
    scan_prefix_kernel<<<BB * INNER / 256, 256>>>(st, alpha, sin);
    scan_apply_kernel<<<BB * NC, 256>>>(
        (const uint2*)ab, sin, (uint2*)g16, conv_w, conv_b,
        alpha, beta, gamma, delta);

    // 5) out = x + g @ Wout^T   (M=32768, N=512, K=1024), fp32 out + residual
    {
        dim3 grid(DD / 128, MM / 128);
        gemm_f16<false><<<grid, 256, GEMM_SMEM_BYTES>>>(g16, wo16, out, x, DD, INNER);
    }
}

// round 15
// speedup vs baseline: 1.2358x; 1.1161x over previous
#include <cuda_runtime.h>
#include <cuda_fp16.h>
#include <cstdint>

// ---------------- problem constants ----------------
#define BB    16
#define KK    2048
#define DD    512
#define INNER 1024
#define W2    (2*INNER)    // combined a|b row stride (halves)
#define KW    5
#define MM    (BB*KK)      // 32768
#define EPSV  1e-5f
#define NC    128          // scan chunks
#define CL    (KK/NC)      // 16
#define RSU2  (W2/4)       // uint2 per ab row (512)
#define USU2  (INNER/4)    // uint2 per g row (256)

// ---------------- scratch (device globals) ----------------
__device__ __half  g_ab [(size_t)MM * W2];     // [M, 2048]: a | b (fp16) 128MB
__device__ __half  g_h16[(size_t)MM * DD];     // rmsnorm out (fp16)
__device__ __half  g_g16[(size_t)MM * INNER];  // scan out    (fp16)
__device__ __half  g_w2 [W2 * DD];             // [Wa;Wb] fp16
__device__ __half  g_wo16[DD * INNER];
__device__ float   g_state[BB * NC * INNER];   // chunk-local final states
__device__ float   g_sin  [BB * NC * INNER];   // carried-in states

__device__ __forceinline__ uint32_t smem_u32(const void* p) {
    uint32_t a;
    asm("{ .reg .u64 t; cvta.to.shared.u64 t, %1; cvt.u32.u64 %0, t; }"
        : "=r"(a) : "l"(p));
    return a;
}

// fast single-MUFU silu: 0.5c + 0.5c*tanh(0.5c)
__device__ __forceinline__ float silu_fast(float c) {
    float h = 0.5f * c;
    float t;
    asm("tanh.approx.f32 %0, %1;" : "=f"(t) : "f"(h));
    return fmaf(h, t, h);
}

// 4-half <-> 4-float helpers
__device__ __forceinline__ void h4_to_f4(uint2 v, float* f) {
    __half2 lo = *reinterpret_cast<__half2*>(&v.x);
    __half2 hi = *reinterpret_cast<__half2*>(&v.y);
    float2 a = __half22float2(lo), b = __half22float2(hi);
    f[0] = a.x; f[1] = a.y; f[2] = b.x; f[3] = b.y;
}
__device__ __forceinline__ uint2 f4_to_h4(const float* f) {
    __half2 lo = __floats2half2_rn(f[0], f[1]);
    __half2 hi = __floats2half2_rn(f[2], f[3]);
    uint2 r;
    r.x = *reinterpret_cast<uint32_t*>(&lo);
    r.y = *reinterpret_cast<uint32_t*>(&hi);
    return r;
}

// ---------------- rmsnorm -> fp16 ----------------
__global__ __launch_bounds__(256) void rmsnorm_kernel(
    const float* __restrict__ x, const float* __restrict__ w,
    __half* __restrict__ h16)
{
    int row  = blockIdx.x * 8 + (threadIdx.x >> 5);
    int lane = threadIdx.x & 31;
    const float4* xp = reinterpret_cast<const float4*>(x + (size_t)row * DD);
    const float4* wp = reinterpret_cast<const float4*>(w);

    float4 v[4];
    float ss = 0.f;
#pragma unroll
    for (int j = 0; j < 4; j++) {
        v[j] = xp[lane + 32 * j];
        ss += v[j].x * v[j].x + v[j].y * v[j].y + v[j].z * v[j].z + v[j].w * v[j].w;
    }
#pragma unroll
    for (int off = 16; off > 0; off >>= 1)
        ss += __shfl_xor_sync(0xffffffffu, ss, off);

    float r = rsqrtf(ss * (1.0f / DD) + EPSV);

    __half* hb = h16 + (size_t)row * DD;
#pragma unroll
    for (int j = 0; j < 4; j++) {
        float4 wv = wp[lane + 32 * j];
        int col = (lane + 32 * j) * 4;
        __half2* hp = reinterpret_cast<__half2*>(hb + col);
        hp[0] = __floats2half2_rn(v[j].x * r * wv.x, v[j].y * r * wv.y);
        hp[1] = __floats2half2_rn(v[j].z * r * wv.z, v[j].w * r * wv.w);
    }
}

// ---------------- combined fp32 -> fp16 cast (all three weights) ------------
#define CVT_N4 (INNER * DD / 4)
__global__ __launch_bounds__(256) void cvt_all_kernel(
    const float* __restrict__ Wa, const float* __restrict__ Wb,
    const float* __restrict__ Wo,
    __half* __restrict__ w2, __half* __restrict__ wo16)
{
    int i = blockIdx.x * 256 + threadIdx.x;
    const float* src;
    __half* dst;
    int o;
    if (i < CVT_N4)            { src = Wa; dst = w2;                        o = i; }
    else if (i < 2 * CVT_N4)   { src = Wb; dst = w2 + (size_t)INNER * DD;   o = i - CVT_N4; }
    else                       { src = Wo; dst = wo16;                      o = i - 2 * CVT_N4; }
    float4 v = reinterpret_cast<const float4*>(src)[o];
    __half2* d = reinterpret_cast<__half2*>(dst) + o * 2;
    d[0] = __floats2half2_rn(v.x, v.y);
    d[1] = __floats2half2_rn(v.z, v.w);
}

// ---------------- HMMA fp16 GEMM with ldmatrix, 4-stage pipeline ------------
// cp.async issue split into two halves bracketing slab-0 compute to spread
// LSU/L1-port pressure away from the post-barrier LDSM burst.
#define RS 40
#define TILE_H (128 * RS)
#define TB (TILE_H * 2)
#define STAGE_B (2 * TB)
#define NSTAGE 4
#define GEMM_SMEM_BYTES (NSTAGE * STAGE_B)   // 81920

#define MMA_F16(c, a, b)                                                \
    asm volatile(                                                       \
        "mma.sync.aligned.m16n8k16.row.col.f32.f16.f16.f32 "            \
        "{%0,%1,%2,%3}, {%4,%5,%6,%7}, {%8,%9}, {%0,%1,%2,%3};"         \
        : "+f"((c)[0]), "+f"((c)[1]), "+f"((c)[2]), "+f"((c)[3])        \
        : "r"((a)[0]), "r"((a)[1]), "r"((a)[2]), "r"((a)[3]),           \
          "r"((b)[0]), "r"((b)[1]))

#define LDSM4(r0, r1, r2, r3, addr)                                     \
    asm volatile("ldmatrix.sync.aligned.m8n8.x4.shared.b16 "            \
                 "{%0,%1,%2,%3}, [%4];"                                 \
                 : "=r"(r0), "=r"(r1), "=r"(r2), "=r"(r3) : "r"(addr))

template <bool HALF_OUT>
__global__ __launch_bounds__(256, 2) void gemm_f16(
    const __half* __restrict__ A, const __half* __restrict__ B,
    void* __restrict__ Cv, const float* __restrict__ res, int N, int K)
{
    extern __shared__ uint16_t sm[];

    const int tid  = threadIdx.x;
    const int lane = tid & 31;
    const int wid  = tid >> 5;
    const int wm   = wid >> 2;
    const int wn   = wid & 3;
    const int r    = lane >> 2;
    const int cp   = (lane & 3) * 2;

    const size_t mBase = (size_t)blockIdx.y * 128;
    const size_t nBase = (size_t)blockIdx.x * 128;

    const __half* srcA = A + mBase * K;
    const __half* srcB = B + nBase * K;

    const uint32_t smem_base = smem_u32(sm);

    const uint32_t aLaneOff =
        (uint32_t)(((wm * 64 + ((lane >> 3) & 1) * 8 + (lane & 7)) * RS
                    + (lane >> 4) * 8) * 2);
    const uint32_t bLaneOff =
        (uint32_t)(((wn * 32 + ((lane >> 4) & 1) * 8 + (lane & 7)) * RS
                    + ((lane >> 3) & 1) * 8) * 2);

    const int lrow0 = tid >> 2;
    const int lseg  = tid & 3;

    // phase 1: rows [0,64) of both tiles (no commit)
    auto load_p1 = [&](int s, int kt) {
        uint32_t sb = smem_base + (uint32_t)s * STAGE_B;
        uint32_t off = lrow0 * (RS * 2) + lseg * 16;
        size_t go = (size_t)lrow0 * K + kt * 32 + lseg * 8;
        asm volatile("cp.async.cg.shared.global [%0], [%1], 16;"
                     :: "r"(sb + off), "l"(srcA + go));
        asm volatile("cp.async.cg.shared.global [%0], [%1], 16;"
                     :: "r"(sb + TB + off), "l"(srcB + go));
    };
    // phase 2: rows [64,128) of both tiles + commit
    auto load_p2 = [&](int s, int kt) {
        uint32_t sb = smem_base + (uint32_t)s * STAGE_B;
        int row = lrow0 + 64;
        uint32_t off = row * (RS * 2) + lseg * 16;
        size_t go = (size_t)row * K + kt * 32 + lseg * 8;
        asm volatile("cp.async.cg.shared.global [%0], [%1], 16;"
                     :: "r"(sb + off), "l"(srcA + go));
        asm volatile("cp.async.cg.shared.global [%0], [%1], 16;"
                     :: "r"(sb + TB + off), "l"(srcB + go));
        asm volatile("cp.async.commit_group;" ::: "memory");
    };

    float acc[4][4][4];
#pragma unroll
    for (int i = 0; i < 4; i++)
#pragma unroll
        for (int j = 0; j < 4; j++)
#pragma unroll
            for (int q = 0; q < 4; q++) acc[i][j][q] = 0.f;

    const int nkt = K >> 5;

    load_p1(0, 0); load_p2(0, 0);
    load_p1(1, 1); load_p2(1, 1);
    load_p1(2, 2); load_p2(2, 2);

    int sc = 0;                       // stage of kt (kt % 4)
    for (int kt = 0; kt < nkt; kt++) {
        int rem = nkt - 1 - kt;       // groups that may stay outstanding
        if (rem >= 2) {
            asm volatile("cp.async.wait_group 2;" ::: "memory");
        } else if (rem == 1) {
            asm volatile("cp.async.wait_group 1;" ::: "memory");
        } else {
            asm volatile("cp.async.wait_group 0;" ::: "memory");
        }
        __syncthreads();   // also guarantees all warps finished compute kt-1

        const bool pf = (kt + 3 < nkt);
        int s3 = sc + 3; if (s3 >= NSTAGE) s3 -= NSTAGE;
        if (pf) load_p1(s3, kt + 3);   // half the LSU burst up front

        uint32_t sb = smem_base + (uint32_t)sc * STAGE_B;

#pragma unroll
        for (int k16 = 0; k16 < 32; k16 += 16) {
            uint32_t bh[4][2];
#pragma unroll
            for (int j = 0; j < 2; j++) {
                uint32_t ad = sb + TB + bLaneOff
                            + (uint32_t)((j * 16 * RS + k16) * 2);
                LDSM4(bh[2*j][0], bh[2*j][1], bh[2*j+1][0], bh[2*j+1][1], ad);
            }
#pragma unroll
            for (int mi = 0; mi < 4; mi++) {
                uint32_t a4[4];
                uint32_t ad = sb + aLaneOff + (uint32_t)((mi * 16 * RS + k16) * 2);
                LDSM4(a4[0], a4[1], a4[2], a4[3], ad);
#pragma unroll
                for (int ni = 0; ni < 4; ni++)
                    MMA_F16(acc[mi][ni], a4, bh[ni]);
            }
            if (k16 == 0 && pf) load_p2(s3, kt + 3);  // second half + commit
        }
        if (++sc == NSTAGE) sc = 0;
    }

#pragma unroll
    for (int mi = 0; mi < 4; mi++) {
        size_t row0 = mBase + wm * 64 + mi * 16 + r;
#pragma unroll
        for (int ni = 0; ni < 4; ni++) {
            size_t col = nBase + wn * 32 + ni * 8 + cp;
            if (HALF_OUT) {
                __half* C = (__half*)Cv;
                *reinterpret_cast<__half2*>(C + row0 * N + col) =
                    __floats2half2_rn(acc[mi][ni][0], acc[mi][ni][1]);
                *reinterpret_cast<__half2*>(C + (row0 + 8) * N + col) =
                    __floats2half2_rn(acc[mi][ni][2], acc[mi][ni][3]);
            } else {
                float* C = (float*)Cv;
                float2 v0 = make_float2(acc[mi][ni][0], acc[mi][ni][1]);
                float2 v1 = make_float2(acc[mi][ni][2], acc[mi][ni][3]);
                if (res) {
                    float2 r0 = *reinterpret_cast<const float2*>(res + row0 * N + col);
                    float2 r1 = *reinterpret_cast<const float2*>(res + (row0 + 8) * N + col);
                    v0.x += r0.x; v0.y += r0.y;
                    v1.x += r1.x; v1.y += r1.y;
                }
                *reinterpret_cast<float2*>(C + row0 * N + col) = v0;
                *reinterpret_cast<float2*>(C + (row0 + 8) * N + col) = v1;
            }
        }
    }
}

// ---------------- scan pass 1: conv+silu -> chunk states only ---------------
__global__ __launch_bounds__(256, 3) void scan_state_kernel(
    const uint2* __restrict__ ab,
    const float* __restrict__ conv_w, const float* __restrict__ conv_b,
    const float* __restrict__ alpha, const float* __restrict__ beta,
    float* __restrict__ S)
{
    const int c = blockIdx.x & (NC - 1);
    const int b = blockIdx.x >> 7;
    const int t = threadIdx.x;
    const int i0 = t * 4;

    float w0[4], w1[4], w2[4], w3[4], w4[4], cb[4], as[4], bt[4];
#pragma unroll
    for (int l = 0; l < 4; l++) {
        w0[l] = conv_w[(i0+l)*KW+0];
        w1[l] = conv_w[(i0+l)*KW+1];
        w2[l] = conv_w[(i0+l)*KW+2];
        w3[l] = conv_w[(i0+l)*KW+3];
        w4[l] = conv_w[(i0+l)*KW+4];
        cb[l] = conv_b[i0+l];
        as[l] = 1.0f / (1.0f + __expf(-alpha[i0+l]));
        bt[l] = beta[i0+l];
    }

    const uint2* col = ab + (size_t)b * KK * RSU2 + t;
    const int k0 = c * CL;

    float xm2[4] = {0,0,0,0}, xm1[4] = {0,0,0,0}, x0[4], x1[4], s[4] = {0,0,0,0};
    if (c > 0) {
        h4_to_f4(col[(size_t)(k0-2) * RSU2], xm2);
        h4_to_f4(col[(size_t)(k0-1) * RSU2], xm1);
    }
    h4_to_f4(col[(size_t)k0 * RSU2], x0);
    h4_to_f4(col[(size_t)(k0+1) * RSU2], x1);

#pragma unroll
    for (int k = 0; k < CL; k += 4) {
        uint2 xr[4];
#pragma unroll
        for (int j = 0; j < 4; j++) {
            int kk = k0 + k + 2 + j;
            xr[j] = (kk < KK) ? col[(size_t)kk * RSU2] : make_uint2(0u, 0u);
        }
#pragma unroll
        for (int j = 0; j < 4; j++) {
            float x2[4];
            h4_to_f4(xr[j], x2);
#pragma unroll
            for (int l = 0; l < 4; l++) {
                float cc = fmaf(w0[l], xm2[l], fmaf(w1[l], xm1[l],
                           fmaf(w2[l], x0[l], fmaf(w3[l], x1[l],
                           fmaf(w4[l], x2[l], cb[l])))));
                float uu = silu_fast(cc);
                s[l] = fmaf(as[l], s[l], bt[l] * uu);
                xm2[l] = xm1[l]; xm1[l] = x0[l]; x0[l] = x1[l]; x1[l] = x2[l];
            }
        }
    }

    *reinterpret_cast<float4*>(&S[((size_t)b * NC + c) * INNER + i0]) =
        make_float4(s[0], s[1], s[2], s[3]);
}

// ---------------- scan pass 2: prefix of chunk states ----------------
__global__ __launch_bounds__(256) void scan_prefix_kernel(
    const float* __restrict__ S, const float* __restrict__ alpha,
    float* __restrict__ Sin)
{
    int idx = blockIdx.x * 256 + threadIdx.x;   // 0 .. BB*INNER-1
    int i = idx & (INNER - 1);
    int b = idx >> 10;

    float a = 1.0f / (1.0f + __expf(-alpha[i]));
    float aL = a;
#pragma unroll
    for (int q = 0; q < 4; q++) aL *= aL;       // a^16

    float s = 0.f;
#pragma unroll
    for (int c = 0; c < NC; c++) {
        size_t o = ((size_t)b * NC + c) * INNER + i;
        Sin[o] = s;
        s = fmaf(aL, s, S[o]);
    }
}

// ---------------- scan pass 3: recompute conv+silu, apply, gate -> g --------
__global__ __launch_bounds__(256, 3) void scan_apply_kernel(
    const uint2* __restrict__ ab,
    const float* __restrict__ Sin,
    uint2* __restrict__ g,
    const float* __restrict__ conv_w, const float* __restrict__ conv_b,
    const float* __restrict__ alpha, const float* __restrict__ beta,
    const float* __restrict__ gamma, const float* __restrict__ delta)
{
    const int c = blockIdx.x & (NC - 1);
    const int b = blockIdx.x >> 7;
    const int t = threadIdx.x;
    const int i0 = t * 4;

    float w0[4], w1[4], w2[4], w3[4], w4[4], cb[4], as[4], bt[4], gm[4], dl[4];
#pragma unroll
    for (int l = 0; l < 4; l++) {
        w0[l] = conv_w[(i0+l)*KW+0];
        w1[l] = conv_w[(i0+l)*KW+1];
        w2[l] = conv_w[(i0+l)*KW+2];
        w3[l] = conv_w[(i0+l)*KW+3];
        w4[l] = conv_w[(i0+l)*KW+4];
        cb[l] = conv_b[i0+l];
        as[l] = 1.0f / (1.0f + __expf(-alpha[i0+l]));
        bt[l] = beta[i0+l];
        gm[l] = gamma[i0+l];
        dl[l] = delta[i0+l];
    }

    const uint2* col = ab + (size_t)b * KK * RSU2 + t;
    const uint2* bp  = col + (RSU2 / 2);
    uint2* gp = g + (size_t)b * KK * USU2 + t;
    const int k0 = c * CL;

    float s[4];
    {
        float4 sv = *reinterpret_cast<const float4*>(
            &Sin[((size_t)b * NC + c) * INNER + i0]);
        s[0] = sv.x; s[1] = sv.y; s[2] = sv.z; s[3] = sv.w;
    }

    float xm2[4] = {0,0,0,0}, xm1[4] = {0,0,0,0}, x0[4], x1[4];
    if (c > 0) {
        h4_to_f4(col[(size_t)(k0-2) * RSU2], xm2);
        h4_to_f4(col[(size_t)(k0-1) * RSU2], xm1);
    }
    h4_to_f4(col[(size_t)k0 * RSU2], x0);
    h4_to_f4(col[(size_t)(k0+1) * RSU2], x1);

#pragma unroll
    for (int k = 0; k < CL; k += 4) {
        uint2 xr[4], br[4];
#pragma unroll
        for (int j = 0; j < 4; j++) {
            int kk = k0 + k + 2 + j;
            xr[j] = (kk < KK) ? col[(size_t)kk * RSU2] : make_uint2(0u, 0u);
        }
#pragma unroll
        for (int j = 0; j < 4; j++)
            br[j] = bp[(size_t)(k0 + k + j) * RSU2];
#pragma unroll
        for (int j = 0; j < 4; j++) {
            float x2[4], bf[4], gf[4];
            h4_to_f4(xr[j], x2);
            h4_to_f4(br[j], bf);
#pragma unroll
            for (int l = 0; l < 4; l++) {
                float cc = fmaf(w0[l], xm2[l], fmaf(w1[l], xm1[l],
                           fmaf(w2[l], x0[l], fmaf(w3[l], x1[l],
                           fmaf(w4[l], x2[l], cb[l])))));
                float uu = silu_fast(cc);
                s[l] = fmaf(as[l], s[l], bt[l] * uu);
                float y = fmaf(gm[l], s[l], dl[l] * uu);
                gf[l] = y * bf[l];
                xm2[l] = xm1[l]; xm1[l] = x0[l]; x0[l] = x1[l]; x1[l] = x2[l];
            }
            gp[(size_t)(k0 + k + j) * USU2] = f4_to_h4(gf);
        }
    }
}

// ---------------- launch (serialized, single stream) ------------------------
extern "C" void kernel_launch(void* const* d_in, const int* in_sizes, int n_in,
                              void* d_out, int out_size)
{
    const float* x      = (const float*)d_in[0];
    const float* norm_w = (const float*)d_in[1];
    const float* Wa     = (const float*)d_in[2];
    const float* Wb     = (const float*)d_in[3];
    const float* conv_w = (const float*)d_in[4];
    const float* conv_b = (const float*)d_in[5];
    const float* alpha  = (const float*)d_in[6];
    const float* beta   = (const float*)d_in[7];
    const float* gamma  = (const float*)d_in[8];
    const float* delta  = (const float*)d_in[9];
    const float* Wout   = (const float*)d_in[10];
    float* out = (float*)d_out;

    float *st, *sin;
    __half *ab, *h16, *g16, *w2, *wo16;
    cudaGetSymbolAddress((void**)&ab,   g_ab);
    cudaGetSymbolAddress((void**)&st,   g_state);
    cudaGetSymbolAddress((void**)&sin,  g_sin);
    cudaGetSymbolAddress((void**)&h16,  g_h16);
    cudaGetSymbolAddress((void**)&g16,  g_g16);
    cudaGetSymbolAddress((void**)&w2,   g_w2);
    cudaGetSymbolAddress((void**)&wo16, g_wo16);

    cudaFuncSetAttribute(gemm_f16<true>,
                         cudaFuncAttributeMaxDynamicSharedMemorySize, GEMM_SMEM_BYTES);
    cudaFuncSetAttribute(gemm_f16<false>,
                         cudaFuncAttributeMaxDynamicSharedMemorySize, GEMM_SMEM_BYTES);

    // 1) rmsnorm -> fp16
    rmsnorm_kernel<<<MM / 8, 256>>>(x, norm_w, h16);

    // 2) all weight conversions in one launch
    cvt_all_kernel<<<(3 * CVT_N4) / 256, 256>>>(Wa, Wb, Wout, w2, wo16);

    // 3) [a|b] = h @ [Wa;Wb]^T   (M=32768, N=2048, K=512), fp16 out
    {
        dim3 grid(W2 / 128, MM / 128);
        gemm_f16<true><<<grid, 256, GEMM_SMEM_BYTES>>>(h16, w2, ab, nullptr, W2, DD);
    }

    // 4) chunked scan: states, prefix, apply(recompute silu)
    scan_state_kernel<<<BB * NC, 256>>>(
        (const uint2*)ab, conv_w, conv_b, alpha, beta, st);
    scan_prefix_kernel<<<BB * INNER / 256, 256>>>(st, alpha, sin);
    scan_apply_kernel<<<BB * NC, 256>>>(
        (const uint2*)ab, sin, (uint2*)g16, conv_w, conv_b,
        alpha, beta, gamma, delta);

    // 5) out = x + g @ Wout^T   (M=32768, N=512, K=1024), fp32 out + residual
    {
        dim3 grid(DD / 128, MM / 128);
        gemm_f16<false><<<grid, 256, GEMM_SMEM_BYTES>>>(g16, wo16, out, x, DD, INNER);
    }
}